// round 1
// baseline (speedup 1.0000x reference)
#include <cuda_runtime.h>
#include <cstdint>

#define B_    64
#define T_    512
#define H_    8
#define D_    32
#define C_    256
#define M_    (B_*T_)          // 32768 packed tokens
#define NTOT  24576
#define QKV_ELEMS (B_*H_*T_*D_)   // 8388608 floats per tensor

// Scratch (device globals: allocation-free per harness rules)
__device__ float g_qkv[3 * QKV_ELEMS];        // q, k, v in [B,H,T,D]
__device__ float g_y[M_ * C_];                // attention output, packed [b*T+t][h*32+d]

// ---------------------------------------------------------------------------
// Tiled fp32 GEMM core: C[M,256] = gather(A) @ W^T + bias
// BM=128, BN=64, BK=32, 256 threads, 8x4 register tile.
// As stored k-major [32][128], Bs k-major [32][64] for float4 fragment loads.
// ---------------------------------------------------------------------------

__global__ __launch_bounds__(256) void gemm_qkv_kernel(
    const float* __restrict__ x, const int* __restrict__ pidx,
    const float* __restrict__ W0, const float* __restrict__ W1, const float* __restrict__ W2,
    const float* __restrict__ b0, const float* __restrict__ b1, const float* __restrict__ b2)
{
    __shared__ float As[32][128];
    __shared__ float Bs[32][64];

    const int z = blockIdx.z;
    const float* __restrict__ W    = (z == 0) ? W0 : (z == 1 ? W1 : W2);
    const float* __restrict__ bias = (z == 0) ? b0 : (z == 1 ? b1 : b2);
    float* __restrict__ out = g_qkv + (size_t)z * QKV_ELEMS;

    const int tid = threadIdx.x;
    const int m0 = blockIdx.x * 128;
    const int n0 = blockIdx.y * 64;
    const int kq = tid & 7;     // which float4 within a 32-col k-chunk
    const int rb = tid >> 3;    // 0..31

    // Per-thread gathered A row pointers (4 rows, stride 32)
    const float* arp[4];
#pragma unroll
    for (int l = 0; l < 4; l++) {
        int r = rb + 32 * l;
        arp[l] = x + (size_t)pidx[m0 + r] * 256 + kq * 4;
    }
    // B (weight) row pointers (2 rows, stride 32)
    const float* brp[2];
#pragma unroll
    for (int l = 0; l < 2; l++) {
        int o = rb + 32 * l;
        brp[l] = W + (size_t)(n0 + o) * 256 + kq * 4;
    }

    float acc[8][4];
#pragma unroll
    for (int i = 0; i < 8; i++)
#pragma unroll
        for (int j = 0; j < 4; j++) acc[i][j] = 0.f;

    const int ty = tid >> 4;   // 0..15 -> 8 rows each
    const int tx = tid & 15;   // 0..15 -> 4 cols each

    for (int k0 = 0; k0 < 256; k0 += 32) {
#pragma unroll
        for (int l = 0; l < 4; l++) {
            float4 v = *(const float4*)(arp[l] + k0);
            int r = rb + 32 * l;
            As[kq*4+0][r] = v.x; As[kq*4+1][r] = v.y;
            As[kq*4+2][r] = v.z; As[kq*4+3][r] = v.w;
        }
#pragma unroll
        for (int l = 0; l < 2; l++) {
            float4 v = *(const float4*)(brp[l] + k0);
            int o = rb + 32 * l;
            Bs[kq*4+0][o] = v.x; Bs[kq*4+1][o] = v.y;
            Bs[kq*4+2][o] = v.z; Bs[kq*4+3][o] = v.w;
        }
        __syncthreads();
#pragma unroll
        for (int k = 0; k < 32; k++) {
            float4 a0 = *(const float4*)&As[k][ty*8];
            float4 a1 = *(const float4*)&As[k][ty*8+4];
            float4 bb = *(const float4*)&Bs[k][tx*4];
            float a[8] = {a0.x,a0.y,a0.z,a0.w,a1.x,a1.y,a1.z,a1.w};
            float bv[4] = {bb.x,bb.y,bb.z,bb.w};
#pragma unroll
            for (int i = 0; i < 8; i++)
#pragma unroll
                for (int j = 0; j < 4; j++) acc[i][j] += a[i] * bv[j];
        }
        __syncthreads();
    }

    // Epilogue: write into [B,H,T,D] head layout
#pragma unroll
    for (int j = 0; j < 4; j++) {
        int o = n0 + tx*4 + j;
        float bz = bias[o];
        int h = o >> 5, d = o & 31;
#pragma unroll
        for (int i = 0; i < 8; i++) {
            int m = m0 + ty*8 + i;
            int bb = m >> 9, tl = m & 511;
            out[(((size_t)(bb * 8 + h)) * 512 + tl) * 32 + d] = acc[i][j] + bz;
        }
    }
}

__global__ __launch_bounds__(256) void gemm_out_kernel(
    const int* __restrict__ pinv, const float* __restrict__ W,
    const float* __restrict__ bias, float* __restrict__ out)
{
    __shared__ float As[32][128];
    __shared__ float Bs[32][64];

    const int tid = threadIdx.x;
    const int m0 = blockIdx.x * 128;
    const int n0 = blockIdx.y * 64;
    const int kq = tid & 7;
    const int rb = tid >> 3;

    const float* arp[4];
#pragma unroll
    for (int l = 0; l < 4; l++) {
        int r = rb + 32 * l;
        arp[l] = g_y + (size_t)pinv[m0 + r] * 256 + kq * 4;
    }
    const float* brp[2];
#pragma unroll
    for (int l = 0; l < 2; l++) {
        int o = rb + 32 * l;
        brp[l] = W + (size_t)(n0 + o) * 256 + kq * 4;
    }

    float acc[8][4];
#pragma unroll
    for (int i = 0; i < 8; i++)
#pragma unroll
        for (int j = 0; j < 4; j++) acc[i][j] = 0.f;

    const int ty = tid >> 4;
    const int tx = tid & 15;

    for (int k0 = 0; k0 < 256; k0 += 32) {
#pragma unroll
        for (int l = 0; l < 4; l++) {
            float4 v = *(const float4*)(arp[l] + k0);
            int r = rb + 32 * l;
            As[kq*4+0][r] = v.x; As[kq*4+1][r] = v.y;
            As[kq*4+2][r] = v.z; As[kq*4+3][r] = v.w;
        }
#pragma unroll
        for (int l = 0; l < 2; l++) {
            float4 v = *(const float4*)(brp[l] + k0);
            int o = rb + 32 * l;
            Bs[kq*4+0][o] = v.x; Bs[kq*4+1][o] = v.y;
            Bs[kq*4+2][o] = v.z; Bs[kq*4+3][o] = v.w;
        }
        __syncthreads();
#pragma unroll
        for (int k = 0; k < 32; k++) {
            float4 a0 = *(const float4*)&As[k][ty*8];
            float4 a1 = *(const float4*)&As[k][ty*8+4];
            float4 bb = *(const float4*)&Bs[k][tx*4];
            float a[8] = {a0.x,a0.y,a0.z,a0.w,a1.x,a1.y,a1.z,a1.w};
            float bv[4] = {bb.x,bb.y,bb.z,bb.w};
#pragma unroll
            for (int i = 0; i < 8; i++)
#pragma unroll
                for (int j = 0; j < 4; j++) acc[i][j] += a[i] * bv[j];
        }
        __syncthreads();
    }

#pragma unroll
    for (int j = 0; j < 4; j++) {
        int o = n0 + tx*4 + j;
        float bz = bias[o];
#pragma unroll
        for (int i = 0; i < 8; i++) {
            int m = m0 + ty*8 + i;
            out[(size_t)m * 256 + o] = acc[i][j] + bz;
        }
    }
}

// ---------------------------------------------------------------------------
// Attention: one CTA per (b,h). K (padded), V, seg ids in smem.
// Each warp handles 64 queries in groups of 4 (sharing K/V smem traffic).
// Mask rule: seg[q] == seg[j]  -> score = -1e9 (per reference).
// ---------------------------------------------------------------------------

#define ATTN_SMEM ((512*33 + 512*32) * 4 + 512 * 4)

__global__ __launch_bounds__(256, 1) void attn_kernel(const int* __restrict__ pbatch)
{
    extern __shared__ float sm[];
    float* Ks = sm;                       // [512][33] padded
    float* Vs = sm + 512 * 33;            // [512][32]
    int*   seg = (int*)(sm + 512*33 + 512*32);

    const int h = blockIdx.x, b = blockIdx.y;
    const size_t base = ((size_t)(b * H_ + h)) * (T_ * D_);
    const float* __restrict__ Q = g_qkv + base;
    const float* __restrict__ K = g_qkv + (size_t)QKV_ELEMS + base;
    const float* __restrict__ V = g_qkv + 2 * (size_t)QKV_ELEMS + base;

    const int tid = threadIdx.x;
    for (int i = tid; i < (T_ * D_) / 4; i += 256) {
        float4 kv = *(const float4*)(K + i * 4);
        int r = i >> 3, d0 = (i & 7) * 4;
        float* dst = Ks + r * 33 + d0;
        dst[0] = kv.x; dst[1] = kv.y; dst[2] = kv.z; dst[3] = kv.w;
        ((float4*)Vs)[i] = *(const float4*)(V + i * 4);
    }
    for (int i = tid; i < T_; i += 256) seg[i] = pbatch[b * T_ + i];
    __syncthreads();

    const int warp = tid >> 5, lane = tid & 31;
    const float scale = 0.17677669529663688f;   // 1/sqrt(32)

    int sj[16];
#pragma unroll
    for (int c = 0; c < 16; c++) sj[c] = seg[lane + 32 * c];

    for (int g0 = warp * 64; g0 < warp * 64 + 64; g0 += 4) {
        float qv[4]; int sq[4];
#pragma unroll
        for (int g = 0; g < 4; g++) {
            qv[g] = Q[(g0 + g) * D_ + lane];
            sq[g] = seg[g0 + g];
        }

        float s[4][16];
#pragma unroll
        for (int g = 0; g < 4; g++)
#pragma unroll
            for (int c = 0; c < 16; c++) s[g][c] = 0.f;

        // scores: s[g][c] = q[g] . k[lane + 32c]
#pragma unroll 8
        for (int d = 0; d < 32; d++) {
            float q0 = __shfl_sync(0xffffffffu, qv[0], d);
            float q1 = __shfl_sync(0xffffffffu, qv[1], d);
            float q2 = __shfl_sync(0xffffffffu, qv[2], d);
            float q3 = __shfl_sync(0xffffffffu, qv[3], d);
#pragma unroll
            for (int c = 0; c < 16; c++) {
                float kk = Ks[(lane + 32 * c) * 33 + d];
                s[0][c] += q0 * kk; s[1][c] += q1 * kk;
                s[2][c] += q2 * kk; s[3][c] += q3 * kk;
            }
        }

        // mask + scale + softmax (unnormalized exp, divide at end)
        float y[4], li[4];
#pragma unroll
        for (int g = 0; g < 4; g++) {
            float mx = -3.0e38f;
#pragma unroll
            for (int c = 0; c < 16; c++) {
                float sv = (sj[c] == sq[g]) ? -1.0e9f : s[g][c] * scale;
                s[g][c] = sv;
                mx = fmaxf(mx, sv);
            }
#pragma unroll
            for (int o = 16; o > 0; o >>= 1)
                mx = fmaxf(mx, __shfl_xor_sync(0xffffffffu, mx, o));
            float sum = 0.f;
#pragma unroll
            for (int c = 0; c < 16; c++) {
                float e = __expf(s[g][c] - mx);
                s[g][c] = e;
                sum += e;
            }
#pragma unroll
            for (int o = 16; o > 0; o >>= 1)
                sum += __shfl_xor_sync(0xffffffffu, sum, o);
            li[g] = 1.0f / sum;
            y[g] = 0.f;
        }

        // y[g][lane] = sum_j p[g][j] * V[j][lane]
        for (int c = 0; c < 16; c++) {
            float p0 = s[0][c], p1 = s[1][c], p2 = s[2][c], p3 = s[3][c];
            const float* vp = Vs + (32 * c) * 32 + lane;
#pragma unroll
            for (int jj = 0; jj < 32; jj++) {
                float v = vp[jj * 32];
                y[0] += __shfl_sync(0xffffffffu, p0, jj) * v;
                y[1] += __shfl_sync(0xffffffffu, p1, jj) * v;
                y[2] += __shfl_sync(0xffffffffu, p2, jj) * v;
                y[3] += __shfl_sync(0xffffffffu, p3, jj) * v;
            }
        }

#pragma unroll
        for (int g = 0; g < 4; g++)
            g_y[((size_t)(b * T_ + g0 + g)) * C_ + h * D_ + lane] = y[g] * li[g];
    }
}

// ---------------------------------------------------------------------------

extern "C" void kernel_launch(void* const* d_in, const int* in_sizes, int n_in,
                              void* d_out, int out_size)
{
    const float* x    = (const float*)d_in[0];
    const float* Wq   = (const float*)d_in[1];
    const float* bq   = (const float*)d_in[2];
    const float* Wk   = (const float*)d_in[3];
    const float* bk   = (const float*)d_in[4];
    const float* Wv   = (const float*)d_in[5];
    const float* bv   = (const float*)d_in[6];
    const float* Wp   = (const float*)d_in[7];
    const float* bp   = (const float*)d_in[8];
    const int* pidx   = (const int*)d_in[9];
    const int* pbatch = (const int*)d_in[10];
    const int* pinv   = (const int*)d_in[11];
    float* out = (float*)d_out;

    cudaFuncSetAttribute(attn_kernel, cudaFuncAttributeMaxDynamicSharedMemorySize, ATTN_SMEM);

    // 1) gather + QKV projections -> g_qkv in [B,H,T,D]
    gemm_qkv_kernel<<<dim3(M_ / 128, 4, 3), 256>>>(x, pidx, Wq, Wk, Wv, bq, bk, bv);
    // 2) masked attention per (b,h) -> g_y packed [B*T][256]
    attn_kernel<<<dim3(H_, B_), 256, ATTN_SMEM>>>(pbatch);
    // 3) output projection fused with inverse-index scatter -> d_out
    gemm_out_kernel<<<dim3(NTOT / 128, 4), 256>>>(pinv, Wp, bp, out);
}

// round 2
// speedup vs baseline: 1.4271x; 1.4271x over previous
#include <cuda_runtime.h>
#include <cstdint>

#define B_    64
#define T_    512
#define H_    8
#define D_    32
#define C_    256
#define M_    (B_*T_)          // 32768 packed tokens
#define NTOT  24576
#define QKV_ELEMS (B_*H_*T_*D_)

__device__ float g_qkv[3 * QKV_ELEMS];   // q,k,v in [B,H,T,D]
__device__ float g_y[M_ * C_];           // attention output packed [b*T+t][h*32+d]

// ---------------------------------------------------------------------------
// GEMM core: 128x128 block tile, BK=32, 256 threads, 8x8 register tile
// (4+4 split fragments: rows {ty*4, 64+ty*4}, cols {tx*4, 64+tx*4}).
// As/Bs padded to 132 words/row: conflict-free fragment LDS.128,
// 4-way (vs 8-way) STS on the k-major tile stores.
// ---------------------------------------------------------------------------

__global__ __launch_bounds__(256) void gemm_qkv_kernel(
    const float* __restrict__ x, const int* __restrict__ pidx,
    const float* __restrict__ W0, const float* __restrict__ W1, const float* __restrict__ W2,
    const float* __restrict__ b0, const float* __restrict__ b1, const float* __restrict__ b2)
{
    __shared__ float As[32][132];
    __shared__ float Bs[32][132];

    const int z = blockIdx.z;
    const float* __restrict__ W    = (z == 0) ? W0 : (z == 1 ? W1 : W2);
    const float* __restrict__ bias = (z == 0) ? b0 : (z == 1 ? b1 : b2);
    float* __restrict__ out = g_qkv + (size_t)z * QKV_ELEMS;

    const int tid = threadIdx.x;
    const int m0 = blockIdx.x * 128;
    const int n0 = blockIdx.y * 128;
    const int kq = tid & 7;
    const int rb = tid >> 3;

    const float* arp[4];
    const float* brp[4];
#pragma unroll
    for (int l = 0; l < 4; l++) {
        arp[l] = x + (size_t)pidx[m0 + rb + 32*l] * 256 + kq * 4;
        brp[l] = W + (size_t)(n0 + rb + 32*l) * 256 + kq * 4;
    }

    float acc[8][8];
#pragma unroll
    for (int i = 0; i < 8; i++)
#pragma unroll
        for (int j = 0; j < 8; j++) acc[i][j] = 0.f;

    const int ty = tid >> 4;   // 0..15
    const int tx = tid & 15;   // 0..15

    for (int k0 = 0; k0 < 256; k0 += 32) {
#pragma unroll
        for (int l = 0; l < 4; l++) {
            float4 v = *(const float4*)(arp[l] + k0);
            int r = rb + 32*l;
            As[kq*4+0][r] = v.x; As[kq*4+1][r] = v.y;
            As[kq*4+2][r] = v.z; As[kq*4+3][r] = v.w;
        }
#pragma unroll
        for (int l = 0; l < 4; l++) {
            float4 v = *(const float4*)(brp[l] + k0);
            int r = rb + 32*l;
            Bs[kq*4+0][r] = v.x; Bs[kq*4+1][r] = v.y;
            Bs[kq*4+2][r] = v.z; Bs[kq*4+3][r] = v.w;
        }
        __syncthreads();
#pragma unroll
        for (int k = 0; k < 32; k++) {
            float4 a0 = *(const float4*)&As[k][ty*4];
            float4 a1 = *(const float4*)&As[k][64 + ty*4];
            float4 c0 = *(const float4*)&Bs[k][tx*4];
            float4 c1 = *(const float4*)&Bs[k][64 + tx*4];
            float a[8] = {a0.x,a0.y,a0.z,a0.w,a1.x,a1.y,a1.z,a1.w};
            float bb[8] = {c0.x,c0.y,c0.z,c0.w,c1.x,c1.y,c1.z,c1.w};
#pragma unroll
            for (int i = 0; i < 8; i++)
#pragma unroll
                for (int j = 0; j < 8; j++) acc[i][j] += a[i] * bb[j];
        }
        __syncthreads();
    }

#pragma unroll
    for (int j = 0; j < 8; j++) {
        int o = n0 + tx*4 + (j & 3) + ((j >> 2) << 6);
        float bz = bias[o];
        int h = o >> 5, d = o & 31;
#pragma unroll
        for (int i = 0; i < 8; i++) {
            int m = m0 + ty*4 + (i & 3) + ((i >> 2) << 6);
            int bb2 = m >> 9, tl = m & 511;
            out[(((size_t)(bb2 * 8 + h)) * 512 + tl) * 32 + d] = acc[i][j] + bz;
        }
    }
}

__global__ __launch_bounds__(256) void gemm_out_kernel(
    const int* __restrict__ pinv, const float* __restrict__ W,
    const float* __restrict__ bias, float* __restrict__ out)
{
    __shared__ float As[32][132];
    __shared__ float Bs[32][132];

    const int tid = threadIdx.x;
    const int m0 = blockIdx.x * 128;
    const int n0 = blockIdx.y * 128;
    const int kq = tid & 7;
    const int rb = tid >> 3;

    const float* arp[4];
    const float* brp[4];
#pragma unroll
    for (int l = 0; l < 4; l++) {
        arp[l] = g_y + (size_t)pinv[m0 + rb + 32*l] * 256 + kq * 4;
        brp[l] = W + (size_t)(n0 + rb + 32*l) * 256 + kq * 4;
    }

    float acc[8][8];
#pragma unroll
    for (int i = 0; i < 8; i++)
#pragma unroll
        for (int j = 0; j < 8; j++) acc[i][j] = 0.f;

    const int ty = tid >> 4;
    const int tx = tid & 15;

    for (int k0 = 0; k0 < 256; k0 += 32) {
#pragma unroll
        for (int l = 0; l < 4; l++) {
            float4 v = *(const float4*)(arp[l] + k0);
            int r = rb + 32*l;
            As[kq*4+0][r] = v.x; As[kq*4+1][r] = v.y;
            As[kq*4+2][r] = v.z; As[kq*4+3][r] = v.w;
        }
#pragma unroll
        for (int l = 0; l < 4; l++) {
            float4 v = *(const float4*)(brp[l] + k0);
            int r = rb + 32*l;
            Bs[kq*4+0][r] = v.x; Bs[kq*4+1][r] = v.y;
            Bs[kq*4+2][r] = v.z; Bs[kq*4+3][r] = v.w;
        }
        __syncthreads();
#pragma unroll
        for (int k = 0; k < 32; k++) {
            float4 a0 = *(const float4*)&As[k][ty*4];
            float4 a1 = *(const float4*)&As[k][64 + ty*4];
            float4 c0 = *(const float4*)&Bs[k][tx*4];
            float4 c1 = *(const float4*)&Bs[k][64 + tx*4];
            float a[8] = {a0.x,a0.y,a0.z,a0.w,a1.x,a1.y,a1.z,a1.w};
            float bb[8] = {c0.x,c0.y,c0.z,c0.w,c1.x,c1.y,c1.z,c1.w};
#pragma unroll
            for (int i = 0; i < 8; i++)
#pragma unroll
                for (int j = 0; j < 8; j++) acc[i][j] += a[i] * bb[j];
        }
        __syncthreads();
    }

#pragma unroll
    for (int j = 0; j < 8; j++) {
        int o = n0 + tx*4 + (j & 3) + ((j >> 2) << 6);
        float bz = bias[o];
#pragma unroll
        for (int i = 0; i < 8; i++) {
            int m = m0 + ty*4 + (i & 3) + ((i >> 2) << 6);
            out[(size_t)m * 256 + o] = acc[i][j] + bz;
        }
    }
}

// ---------------------------------------------------------------------------
// Attention: one CTA per (b,h). K row-major (stride 36, conflict-free float4),
// V transposed (Vt[32][516], conflict-free float4 over j), per-warp P buffer
// in smem (broadcast float4 reads). All shuffle traffic in PV eliminated.
// Mask rule (per reference): seg[q] == seg[j] -> -1e9.
// ---------------------------------------------------------------------------

#define KS_STRIDE 36
#define VT_STRIDE 516
#define SM_VT  (512*KS_STRIDE)                 // 18432 floats
#define SM_PS  (SM_VT + 32*VT_STRIDE)          // 34944
#define SM_SEG (SM_PS + 8*4*512)               // 51328
#define ATTN_SMEM ((SM_SEG + 512) * 4)         // 207360 bytes

__global__ __launch_bounds__(256, 1) void attn_kernel(const int* __restrict__ pbatch)
{
    extern __shared__ float sm[];
    float* Ks = sm;
    float* Vt = sm + SM_VT;
    int*   seg = (int*)(sm + SM_SEG);

    const int h = blockIdx.x, b = blockIdx.y;
    const size_t base = ((size_t)(b * H_ + h)) * (T_ * D_);
    const float* __restrict__ Q = g_qkv + base;
    const float* __restrict__ K = g_qkv + (size_t)QKV_ELEMS + base;
    const float* __restrict__ V = g_qkv + 2 * (size_t)QKV_ELEMS + base;

    const int tid = threadIdx.x;

    // K -> Ks[j][d], float4, conflict-free
    for (int i = tid; i < 512 * 8; i += 256) {
        float4 kv = *(const float4*)(K + i * 4);
        int j = i >> 3, d4 = i & 7;
        *(float4*)&Ks[j * KS_STRIDE + d4 * 4] = kv;
    }
    // V -> Vt[d][j] transpose (coalesced-enough loads, conflict-free stores)
    for (int i = tid; i < 4096; i += 256) {
        int d4 = i >> 9, j = i & 511;
        float4 v = *(const float4*)(V + j * 32 + d4 * 4);
        Vt[(d4*4+0)*VT_STRIDE + j] = v.x;
        Vt[(d4*4+1)*VT_STRIDE + j] = v.y;
        Vt[(d4*4+2)*VT_STRIDE + j] = v.z;
        Vt[(d4*4+3)*VT_STRIDE + j] = v.w;
    }
    for (int i = tid; i < 512; i += 256) seg[i] = pbatch[b * 512 + i];
    __syncthreads();

    const int warp = tid >> 5, lane = tid & 31;
    float* Ps = sm + SM_PS + warp * 2048;
    const float scale = 0.17677669529663688f;   // 1/sqrt(32)

    int sj[16];
#pragma unroll
    for (int c = 0; c < 16; c++) sj[c] = seg[lane + 32 * c];

    for (int step = 0; step < 16; step++) {
        const int g0 = warp * 64 + step * 4;
        float qv[4]; int sq[4];
#pragma unroll
        for (int g = 0; g < 4; g++) {
            qv[g] = Q[(g0 + g) * D_ + lane];
            sq[g] = seg[g0 + g];
        }

        float s[4][16];
#pragma unroll
        for (int g = 0; g < 4; g++)
#pragma unroll
            for (int c = 0; c < 16; c++) s[g][c] = 0.f;

        // QK: lane owns j = lane + 32c
#pragma unroll
        for (int d4 = 0; d4 < 8; d4++) {
            float qf[4][4];
#pragma unroll
            for (int g = 0; g < 4; g++)
#pragma unroll
                for (int t = 0; t < 4; t++)
                    qf[g][t] = __shfl_sync(0xffffffffu, qv[g], d4 * 4 + t);
#pragma unroll
            for (int c = 0; c < 16; c++) {
                float4 k4 = *(const float4*)&Ks[(lane + 32*c) * KS_STRIDE + d4 * 4];
#pragma unroll
                for (int g = 0; g < 4; g++) {
                    s[g][c] += qf[g][0] * k4.x;
                    s[g][c] += qf[g][1] * k4.y;
                    s[g][c] += qf[g][2] * k4.z;
                    s[g][c] += qf[g][3] * k4.w;
                }
            }
        }

        // mask + softmax (unnormalized exp; divide at the end)
        float li[4];
#pragma unroll
        for (int g = 0; g < 4; g++) {
            float mx = -3.0e38f;
#pragma unroll
            for (int c = 0; c < 16; c++) {
                float sv = (sj[c] == sq[g]) ? -1.0e9f : s[g][c] * scale;
                s[g][c] = sv;
                mx = fmaxf(mx, sv);
            }
#pragma unroll
            for (int o = 16; o > 0; o >>= 1)
                mx = fmaxf(mx, __shfl_xor_sync(0xffffffffu, mx, o));
            float sum = 0.f;
#pragma unroll
            for (int c = 0; c < 16; c++) {
                float e = __expf(s[g][c] - mx);
                s[g][c] = e;
                sum += e;
            }
#pragma unroll
            for (int o = 16; o > 0; o >>= 1)
                sum += __shfl_xor_sync(0xffffffffu, sum, o);
            li[g] = 1.0f / sum;
        }

        __syncwarp();   // prior iteration's Ps reads done
#pragma unroll
        for (int g = 0; g < 4; g++)
#pragma unroll
            for (int c = 0; c < 16; c++)
                Ps[g * 512 + lane + 32 * c] = s[g][c];
        __syncwarp();   // Ps visible to all lanes

        // PV: lane owns d = lane; float4 over j
        float y0 = 0.f, y1 = 0.f, y2 = 0.f, y3 = 0.f;
#pragma unroll 4
        for (int j4 = 0; j4 < 128; j4++) {
            float4 v  = *(const float4*)&Vt[lane * VT_STRIDE + j4 * 4];
            float4 p0 = *(const float4*)&Ps[        j4 * 4];
            float4 p1 = *(const float4*)&Ps[ 512 + j4 * 4];
            float4 p2 = *(const float4*)&Ps[1024 + j4 * 4];
            float4 p3 = *(const float4*)&Ps[1536 + j4 * 4];
            y0 += p0.x*v.x + p0.y*v.y + p0.z*v.z + p0.w*v.w;
            y1 += p1.x*v.x + p1.y*v.y + p1.z*v.z + p1.w*v.w;
            y2 += p2.x*v.x + p2.y*v.y + p2.z*v.z + p2.w*v.w;
            y3 += p3.x*v.x + p3.y*v.y + p3.z*v.z + p3.w*v.w;
        }

        float yo[4] = {y0, y1, y2, y3};
#pragma unroll
        for (int g = 0; g < 4; g++)
            g_y[((size_t)(b * T_ + g0 + g)) * C_ + h * D_ + lane] = yo[g] * li[g];
    }
}

// ---------------------------------------------------------------------------

extern "C" void kernel_launch(void* const* d_in, const int* in_sizes, int n_in,
                              void* d_out, int out_size)
{
    const float* x    = (const float*)d_in[0];
    const float* Wq   = (const float*)d_in[1];
    const float* bq   = (const float*)d_in[2];
    const float* Wk   = (const float*)d_in[3];
    const float* bk   = (const float*)d_in[4];
    const float* Wv   = (const float*)d_in[5];
    const float* bv   = (const float*)d_in[6];
    const float* Wp   = (const float*)d_in[7];
    const float* bp   = (const float*)d_in[8];
    const int* pidx   = (const int*)d_in[9];
    const int* pbatch = (const int*)d_in[10];
    const int* pinv   = (const int*)d_in[11];
    float* out = (float*)d_out;

    cudaFuncSetAttribute(attn_kernel, cudaFuncAttributeMaxDynamicSharedMemorySize, ATTN_SMEM);

    gemm_qkv_kernel<<<dim3(M_ / 128, 2, 3), 256>>>(x, pidx, Wq, Wk, Wv, bq, bk, bv);
    attn_kernel<<<dim3(H_, B_), 256, ATTN_SMEM>>>(pbatch);
    gemm_out_kernel<<<dim3(NTOT / 128, 2), 256>>>(pinv, Wp, bp, out);
}

// round 4
// speedup vs baseline: 2.8828x; 2.0201x over previous
#include <cuda_runtime.h>
#include <cstdint>

#define B_    64
#define T_    512
#define H_    8
#define D_    32
#define C_    256
#define M_    (B_*T_)
#define NTOT  24576
#define QKV_ELEMS (M_*C_)

__device__ float g_qkv[3 * QKV_ELEMS];   // q,k,v each [token][256] row-major
__device__ float g_y[M_ * C_];           // attention out [b*T+t][h*32+d]

// ---------------- mma.sync tf32 helpers (sm_80+ path; no 'a' feature) -------
__device__ __forceinline__ uint32_t f2tf32(float f) {
    uint32_t u; asm("cvt.rna.tf32.f32 %0, %1;" : "=r"(u) : "f"(f)); return u;
}
__device__ __forceinline__ void mma8(float* d, const uint32_t* a, uint32_t b0, uint32_t b1) {
    asm volatile(
        "mma.sync.aligned.m16n8k8.row.col.f32.tf32.tf32.f32 "
        "{%0,%1,%2,%3},{%4,%5,%6,%7},{%8,%9},{%0,%1,%2,%3};"
        : "+f"(d[0]), "+f"(d[1]), "+f"(d[2]), "+f"(d[3])
        : "r"(a[0]), "r"(a[1]), "r"(a[2]), "r"(a[3]), "r"(b0), "r"(b1));
}

// ---------------------------------------------------------------------------
// FFMA GEMM (round-2 proven): 128x128 tile, BK=32, 256 thr, 8x8 frag
// ---------------------------------------------------------------------------
__global__ __launch_bounds__(256) void gemm_qkv_kernel(
    const float* __restrict__ x, const int* __restrict__ pidx,
    const float* __restrict__ W0, const float* __restrict__ W1, const float* __restrict__ W2,
    const float* __restrict__ b0, const float* __restrict__ b1, const float* __restrict__ b2)
{
    __shared__ float As[32][132];
    __shared__ float Bs[32][132];

    const int z = blockIdx.z;
    const float* __restrict__ W    = (z == 0) ? W0 : (z == 1 ? W1 : W2);
    const float* __restrict__ bias = (z == 0) ? b0 : (z == 1 ? b1 : b2);
    float* __restrict__ out = g_qkv + (size_t)z * QKV_ELEMS;

    const int tid = threadIdx.x;
    const int m0 = blockIdx.x * 128;
    const int n0 = blockIdx.y * 128;
    const int kq = tid & 7;
    const int rb = tid >> 3;

    const float* arp[4];
    const float* brp[4];
#pragma unroll
    for (int l = 0; l < 4; l++) {
        arp[l] = x + (size_t)pidx[m0 + rb + 32*l] * 256 + kq * 4;
        brp[l] = W + (size_t)(n0 + rb + 32*l) * 256 + kq * 4;
    }

    float acc[8][8];
#pragma unroll
    for (int i = 0; i < 8; i++)
#pragma unroll
        for (int j = 0; j < 8; j++) acc[i][j] = 0.f;

    const int ty = tid >> 4;
    const int tx = tid & 15;

    for (int k0 = 0; k0 < 256; k0 += 32) {
#pragma unroll
        for (int l = 0; l < 4; l++) {
            float4 v = *(const float4*)(arp[l] + k0);
            int r = rb + 32*l;
            As[kq*4+0][r] = v.x; As[kq*4+1][r] = v.y;
            As[kq*4+2][r] = v.z; As[kq*4+3][r] = v.w;
        }
#pragma unroll
        for (int l = 0; l < 4; l++) {
            float4 v = *(const float4*)(brp[l] + k0);
            int r = rb + 32*l;
            Bs[kq*4+0][r] = v.x; Bs[kq*4+1][r] = v.y;
            Bs[kq*4+2][r] = v.z; Bs[kq*4+3][r] = v.w;
        }
        __syncthreads();
#pragma unroll
        for (int k = 0; k < 32; k++) {
            float4 a0 = *(const float4*)&As[k][ty*4];
            float4 a1 = *(const float4*)&As[k][64 + ty*4];
            float4 c0 = *(const float4*)&Bs[k][tx*4];
            float4 c1 = *(const float4*)&Bs[k][64 + tx*4];
            float a[8] = {a0.x,a0.y,a0.z,a0.w,a1.x,a1.y,a1.z,a1.w};
            float bb[8] = {c0.x,c0.y,c0.z,c0.w,c1.x,c1.y,c1.z,c1.w};
#pragma unroll
            for (int i = 0; i < 8; i++)
#pragma unroll
                for (int j = 0; j < 8; j++) acc[i][j] += a[i] * bb[j];
        }
        __syncthreads();
    }

#pragma unroll
    for (int i = 0; i < 8; i++) {
        int m = m0 + ty*4 + (i & 3) + ((i >> 2) << 6);
#pragma unroll
        for (int jh = 0; jh < 2; jh++) {
            int o = n0 + jh*64 + tx*4;
            float4 v;
            v.x = acc[i][jh*4+0] + bias[o+0];
            v.y = acc[i][jh*4+1] + bias[o+1];
            v.z = acc[i][jh*4+2] + bias[o+2];
            v.w = acc[i][jh*4+3] + bias[o+3];
            *(float4*)&out[(size_t)m * 256 + o] = v;
        }
    }
}

__global__ __launch_bounds__(256) void gemm_out_kernel(
    const int* __restrict__ pinv, const float* __restrict__ W,
    const float* __restrict__ bias, float* __restrict__ out)
{
    __shared__ float As[32][132];
    __shared__ float Bs[32][132];

    const int tid = threadIdx.x;
    const int m0 = blockIdx.x * 128;
    const int n0 = blockIdx.y * 128;
    const int kq = tid & 7;
    const int rb = tid >> 3;

    const float* arp[4];
    const float* brp[4];
#pragma unroll
    for (int l = 0; l < 4; l++) {
        arp[l] = g_y + (size_t)pinv[m0 + rb + 32*l] * 256 + kq * 4;
        brp[l] = W + (size_t)(n0 + rb + 32*l) * 256 + kq * 4;
    }

    float acc[8][8];
#pragma unroll
    for (int i = 0; i < 8; i++)
#pragma unroll
        for (int j = 0; j < 8; j++) acc[i][j] = 0.f;

    const int ty = tid >> 4;
    const int tx = tid & 15;

    for (int k0 = 0; k0 < 256; k0 += 32) {
#pragma unroll
        for (int l = 0; l < 4; l++) {
            float4 v = *(const float4*)(arp[l] + k0);
            int r = rb + 32*l;
            As[kq*4+0][r] = v.x; As[kq*4+1][r] = v.y;
            As[kq*4+2][r] = v.z; As[kq*4+3][r] = v.w;
        }
#pragma unroll
        for (int l = 0; l < 4; l++) {
            float4 v = *(const float4*)(brp[l] + k0);
            int r = rb + 32*l;
            Bs[kq*4+0][r] = v.x; Bs[kq*4+1][r] = v.y;
            Bs[kq*4+2][r] = v.z; Bs[kq*4+3][r] = v.w;
        }
        __syncthreads();
#pragma unroll
        for (int k = 0; k < 32; k++) {
            float4 a0 = *(const float4*)&As[k][ty*4];
            float4 a1 = *(const float4*)&As[k][64 + ty*4];
            float4 c0 = *(const float4*)&Bs[k][tx*4];
            float4 c1 = *(const float4*)&Bs[k][64 + tx*4];
            float a[8] = {a0.x,a0.y,a0.z,a0.w,a1.x,a1.y,a1.z,a1.w};
            float bb[8] = {c0.x,c0.y,c0.z,c0.w,c1.x,c1.y,c1.z,c1.w};
#pragma unroll
            for (int i = 0; i < 8; i++)
#pragma unroll
                for (int j = 0; j < 8; j++) acc[i][j] += a[i] * bb[j];
        }
        __syncthreads();
    }

#pragma unroll
    for (int i = 0; i < 8; i++) {
        int m = m0 + ty*4 + (i & 3) + ((i >> 2) << 6);
#pragma unroll
        for (int jh = 0; jh < 2; jh++) {
            int o = n0 + jh*64 + tx*4;
            float4 v;
            v.x = acc[i][jh*4+0] + bias[o+0];
            v.y = acc[i][jh*4+1] + bias[o+1];
            v.z = acc[i][jh*4+2] + bias[o+2];
            v.w = acc[i][jh*4+3] + bias[o+3];
            *(float4*)&out[(size_t)m * 256 + o] = v;
        }
    }
}

// ---------------------------------------------------------------------------
// Attention via mma.sync tf32, flash-style streaming softmax.
// One CTA per (b,h), 8 warps; warp handles 64 queries in 4 groups of 16.
// Ks[j][d] stride 36 (B-frag conflict-free), Vs[j][d] stride 40 (conflict-free),
// per-warp P buffer [16][68] (A-frag conflict-free).
// Mask: seg[q]==seg[j] -> -1e9 (per reference).
// ---------------------------------------------------------------------------
#define KS_OFF 0
#define VS_OFF (512*36)
#define PS_OFF (VS_OFF + 512*40)
#define SEG_OFF (PS_OFF + 8*1088)
#define ATTN_SMEM ((SEG_OFF + 512) * 4)    // 192512 bytes

__global__ __launch_bounds__(256, 1) void attn_kernel(const int* __restrict__ pbatch)
{
    extern __shared__ uint32_t sm[];
    uint32_t* Ks = sm + KS_OFF;
    uint32_t* Vs = sm + VS_OFF;
    uint32_t* Ps = sm + PS_OFF;
    int*      seg = (int*)(sm + SEG_OFF);

    const int h = blockIdx.x, b = blockIdx.y;
    const float* __restrict__ Qb = g_qkv + (size_t)(b * 512) * 256 + h * 32;
    const float* __restrict__ Kb = Qb + QKV_ELEMS;
    const float* __restrict__ Vb = Qb + 2 * (size_t)QKV_ELEMS;

    const int tid = threadIdx.x;

    // stage K,V as tf32 bits
#pragma unroll
    for (int it = 0; it < 16; it++) {
        int idx = tid + it * 256;          // 0..4095
        int j = idx >> 3, d4 = (idx & 7) * 4;
        float4 kv = *(const float4*)(Kb + (size_t)j * 256 + d4);
        float4 vv = *(const float4*)(Vb + (size_t)j * 256 + d4);
        Ks[j*36 + d4+0] = f2tf32(kv.x); Ks[j*36 + d4+1] = f2tf32(kv.y);
        Ks[j*36 + d4+2] = f2tf32(kv.z); Ks[j*36 + d4+3] = f2tf32(kv.w);
        Vs[j*40 + d4+0] = f2tf32(vv.x); Vs[j*40 + d4+1] = f2tf32(vv.y);
        Vs[j*40 + d4+2] = f2tf32(vv.z); Vs[j*40 + d4+3] = f2tf32(vv.w);
    }
    for (int i = tid; i < 512; i += 256) seg[i] = pbatch[b * 512 + i];
    __syncthreads();

    const int warp = tid >> 5, lane = tid & 31;
    const int g = lane >> 2, c = lane & 3;
    uint32_t* Pw = Ps + warp * 1088;       // [16][68]
    const float scale = 0.17677669529663688f;   // 1/sqrt(32)

    for (int grp = 0; grp < 4; grp++) {
        const int q0 = warp * 64 + grp * 16;
        const int r0 = q0 + g, r1 = q0 + g + 8;
        const float* Q0 = Qb + (size_t)r0 * 256;
        const float* Q1 = Qb + (size_t)r1 * 256;

        uint32_t aq[4][4];
#pragma unroll
        for (int kt = 0; kt < 4; kt++) {
            aq[kt][0] = f2tf32(Q0[kt*8 + c] * scale);
            aq[kt][1] = f2tf32(Q1[kt*8 + c] * scale);
            aq[kt][2] = f2tf32(Q0[kt*8 + c + 4] * scale);
            aq[kt][3] = f2tf32(Q1[kt*8 + c + 4] * scale);
        }
        const int sq0 = seg[r0], sq1 = seg[r1];

        float m0 = -1e30f, m1 = -1e30f, l0 = 0.f, l1 = 0.f;
        float y[4][4];
#pragma unroll
        for (int n = 0; n < 4; n++)
#pragma unroll
            for (int r = 0; r < 4; r++) y[n][r] = 0.f;

        for (int ch = 0; ch < 8; ch++) {
            const int j0 = ch * 64;
            float s[8][4];
#pragma unroll
            for (int nt = 0; nt < 8; nt++) {
                s[nt][0] = s[nt][1] = s[nt][2] = s[nt][3] = 0.f;
                const int jb = (j0 + nt*8 + g) * 36;
#pragma unroll
                for (int kt = 0; kt < 4; kt++)
                    mma8(s[nt], aq[kt], Ks[jb + kt*8 + c], Ks[jb + kt*8 + c + 4]);
            }

            // mask + running max
            float cm0 = m0, cm1 = m1;
#pragma unroll
            for (int nt = 0; nt < 8; nt++) {
                const int jA = j0 + nt*8 + 2*c;
                const int sA = seg[jA], sB = seg[jA + 1];
                if (sA == sq0) s[nt][0] = -1e9f;
                if (sB == sq0) s[nt][1] = -1e9f;
                if (sA == sq1) s[nt][2] = -1e9f;
                if (sB == sq1) s[nt][3] = -1e9f;
                cm0 = fmaxf(cm0, fmaxf(s[nt][0], s[nt][1]));
                cm1 = fmaxf(cm1, fmaxf(s[nt][2], s[nt][3]));
            }
            cm0 = fmaxf(cm0, __shfl_xor_sync(0xffffffffu, cm0, 1));
            cm0 = fmaxf(cm0, __shfl_xor_sync(0xffffffffu, cm0, 2));
            cm1 = fmaxf(cm1, __shfl_xor_sync(0xffffffffu, cm1, 1));
            cm1 = fmaxf(cm1, __shfl_xor_sync(0xffffffffu, cm1, 2));

            const float a0 = __expf(m0 - cm0), a1 = __expf(m1 - cm1);
            m0 = cm0; m1 = cm1;
            l0 *= a0; l1 *= a1;
#pragma unroll
            for (int n = 0; n < 4; n++) {
                y[n][0] *= a0; y[n][1] *= a0;
                y[n][2] *= a1; y[n][3] *= a1;
            }

            float ps0 = 0.f, ps1 = 0.f;
#pragma unroll
            for (int nt = 0; nt < 8; nt++) {
                float p0 = __expf(s[nt][0] - m0);
                float p1 = __expf(s[nt][1] - m0);
                float p2 = __expf(s[nt][2] - m1);
                float p3 = __expf(s[nt][3] - m1);
                ps0 += p0 + p1; ps1 += p2 + p3;
                Pw[g*68      + nt*8 + 2*c    ] = f2tf32(p0);
                Pw[g*68      + nt*8 + 2*c + 1] = f2tf32(p1);
                Pw[(g+8)*68  + nt*8 + 2*c    ] = f2tf32(p2);
                Pw[(g+8)*68  + nt*8 + 2*c + 1] = f2tf32(p3);
            }
            l0 += ps0; l1 += ps1;
            __syncwarp();

            // PV accumulate
#pragma unroll
            for (int kt2 = 0; kt2 < 8; kt2++) {
                uint32_t ap[4];
                ap[0] = Pw[g*68     + kt2*8 + c];
                ap[1] = Pw[(g+8)*68 + kt2*8 + c];
                ap[2] = Pw[g*68     + kt2*8 + c + 4];
                ap[3] = Pw[(g+8)*68 + kt2*8 + c + 4];
                const int vb0 = (j0 + kt2*8 + c) * 40 + g;
                const int vb1 = (j0 + kt2*8 + c + 4) * 40 + g;
#pragma unroll
                for (int nt2 = 0; nt2 < 4; nt2++)
                    mma8(y[nt2], ap, Vs[vb0 + nt2*8], Vs[vb1 + nt2*8]);
            }
            __syncwarp();
        }

        l0 += __shfl_xor_sync(0xffffffffu, l0, 1);
        l0 += __shfl_xor_sync(0xffffffffu, l0, 2);
        l1 += __shfl_xor_sync(0xffffffffu, l1, 1);
        l1 += __shfl_xor_sync(0xffffffffu, l1, 2);
        const float inv0 = 1.0f / l0, inv1 = 1.0f / l1;

        float* O0 = g_y + (size_t)(b * 512 + r0) * 256 + h * 32;
        float* O1 = g_y + (size_t)(b * 512 + r1) * 256 + h * 32;
#pragma unroll
        for (int nt2 = 0; nt2 < 4; nt2++) {
            float2 v0 = make_float2(y[nt2][0] * inv0, y[nt2][1] * inv0);
            float2 v1 = make_float2(y[nt2][2] * inv1, y[nt2][3] * inv1);
            *(float2*)&O0[nt2*8 + 2*c] = v0;
            *(float2*)&O1[nt2*8 + 2*c] = v1;
        }
    }
}

// ---------------------------------------------------------------------------

extern "C" void kernel_launch(void* const* d_in, const int* in_sizes, int n_in,
                              void* d_out, int out_size)
{
    const float* x    = (const float*)d_in[0];
    const float* Wq   = (const float*)d_in[1];
    const float* bq   = (const float*)d_in[2];
    const float* Wk   = (const float*)d_in[3];
    const float* bk   = (const float*)d_in[4];
    const float* Wv   = (const float*)d_in[5];
    const float* bv   = (const float*)d_in[6];
    const float* Wp   = (const float*)d_in[7];
    const float* bp   = (const float*)d_in[8];
    const int* pidx   = (const int*)d_in[9];
    const int* pbatch = (const int*)d_in[10];
    const int* pinv   = (const int*)d_in[11];
    float* out = (float*)d_out;

    cudaFuncSetAttribute(attn_kernel, cudaFuncAttributeMaxDynamicSharedMemorySize, ATTN_SMEM);

    gemm_qkv_kernel<<<dim3(M_ / 128, 2, 3), 256>>>(x, pidx, Wq, Wk, Wv, bq, bk, bv);
    attn_kernel<<<dim3(H_, B_), 256, ATTN_SMEM>>>(pbatch);
    gemm_out_kernel<<<dim3(NTOT / 128, 2), 256>>>(pinv, Wp, bp, out);
}

// round 5
// speedup vs baseline: 4.6544x; 1.6145x over previous
#include <cuda_runtime.h>
#include <cstdint>

#define B_    64
#define T_    512
#define H_    8
#define D_    32
#define C_    256
#define M_    (B_*T_)
#define NTOT  24576
#define QKV_ELEMS (M_*C_)

__device__ float g_qkv[3 * QKV_ELEMS];   // q,k,v each [token][256] row-major
__device__ float g_y[M_ * C_];           // attention out [b*T+t][h*32+d]

// ---------------- mma.sync tf32 helpers --------------------------------------
__device__ __forceinline__ uint32_t f2tf32(float f) {
    uint32_t u; asm("cvt.rna.tf32.f32 %0, %1;" : "=r"(u) : "f"(f)); return u;
}
__device__ __forceinline__ void mma8(float* d, const uint32_t* a, uint32_t b0, uint32_t b1) {
    asm volatile(
        "mma.sync.aligned.m16n8k8.row.col.f32.tf32.tf32.f32 "
        "{%0,%1,%2,%3},{%4,%5,%6,%7},{%8,%9},{%0,%1,%2,%3};"
        : "+f"(d[0]), "+f"(d[1]), "+f"(d[2]), "+f"(d[3])
        : "r"(a[0]), "r"(a[1]), "r"(a[2]), "r"(a[3]), "r"(b0), "r"(b1));
}

// ---------------------------------------------------------------------------
// tf32 tensor-core GEMM: C[128,128] = gather(A)[128,256] @ W[n0:,256]^T + bias
// BK=32 double-buffered; A/W staged as tf32, stride 36 (conflict-free frags).
// 8 warps, warp tile 64x32 (4x4 m16n8k8), K=256.
// ---------------------------------------------------------------------------
#define GSM_STRIDE 36
#define GSM_BUF (128 * GSM_STRIDE)          // words per operand buffer
#define GEMM_SMEM (4 * GSM_BUF * 4)         // 73728 bytes

__device__ __forceinline__ void gemm_tc_core(
    const float* __restrict__ A, const int* __restrict__ gidx,
    const float* __restrict__ W, const float* __restrict__ bias,
    float* __restrict__ outp, int m0, int n0, uint32_t* smg)
{
    uint32_t* As = smg;                  // [2][128*36]
    uint32_t* Ws = smg + 2 * GSM_BUF;    // [2][128*36]

    const int tid = threadIdx.x;
    const int rb = tid >> 3;             // 0..31
    const int kq = tid & 7;              // float4 col within 32-col chunk

    const float* arp[4];
    const float* wrp[4];
    int sofs[4];
#pragma unroll
    for (int l = 0; l < 4; l++) {
        int r = rb + 32 * l;
        arp[l] = A + (size_t)gidx[m0 + r] * 256 + kq * 4;
        wrp[l] = W + (size_t)(n0 + r) * 256 + kq * 4;
        sofs[l] = r * GSM_STRIDE + kq * 4;
    }

    float4 va[4], vw[4];
    auto load_regs = [&](int c) {
        const int k0 = c * 32;
#pragma unroll
        for (int l = 0; l < 4; l++) {
            va[l] = *(const float4*)(arp[l] + k0);
            vw[l] = *(const float4*)(wrp[l] + k0);
        }
    };
    auto store_smem = [&](int buf) {
        uint32_t* Ab = As + buf * GSM_BUF;
        uint32_t* Wb = Ws + buf * GSM_BUF;
#pragma unroll
        for (int l = 0; l < 4; l++) {
            uint32_t* pa = Ab + sofs[l];
            pa[0] = f2tf32(va[l].x); pa[1] = f2tf32(va[l].y);
            pa[2] = f2tf32(va[l].z); pa[3] = f2tf32(va[l].w);
            uint32_t* pw = Wb + sofs[l];
            pw[0] = f2tf32(vw[l].x); pw[1] = f2tf32(vw[l].y);
            pw[2] = f2tf32(vw[l].z); pw[3] = f2tf32(vw[l].w);
        }
    };

    const int warp = tid >> 5, lane = tid & 31;
    const int g = lane >> 2, c = lane & 3;
    const int wm = warp >> 2, wn = warp & 3;
    const int mb = wm * 64, nb = wn * 32;

    float acc[4][4][4];
#pragma unroll
    for (int mi = 0; mi < 4; mi++)
#pragma unroll
        for (int ni = 0; ni < 4; ni++)
#pragma unroll
            for (int t = 0; t < 4; t++) acc[mi][ni][t] = 0.f;

    load_regs(0);
    store_smem(0);
    __syncthreads();

    for (int ch = 0; ch < 8; ch++) {
        if (ch < 7) load_regs(ch + 1);

        const uint32_t* Ab = As + (ch & 1) * GSM_BUF;
        const uint32_t* Wb = Ws + (ch & 1) * GSM_BUF;
#pragma unroll
        for (int kt = 0; kt < 4; kt++) {
            uint32_t af[4][4];
#pragma unroll
            for (int mi = 0; mi < 4; mi++) {
                const int r = mb + mi * 16 + g;
                af[mi][0] = Ab[r * GSM_STRIDE + kt*8 + c];
                af[mi][1] = Ab[(r + 8) * GSM_STRIDE + kt*8 + c];
                af[mi][2] = Ab[r * GSM_STRIDE + kt*8 + c + 4];
                af[mi][3] = Ab[(r + 8) * GSM_STRIDE + kt*8 + c + 4];
            }
            uint32_t bf[4][2];
#pragma unroll
            for (int ni = 0; ni < 4; ni++) {
                const int rn = nb + ni * 8 + g;
                bf[ni][0] = Wb[rn * GSM_STRIDE + kt*8 + c];
                bf[ni][1] = Wb[rn * GSM_STRIDE + kt*8 + c + 4];
            }
#pragma unroll
            for (int mi = 0; mi < 4; mi++)
#pragma unroll
                for (int ni = 0; ni < 4; ni++)
                    mma8(acc[mi][ni], af[mi], bf[ni][0], bf[ni][1]);
        }

        if (ch < 7) {
            store_smem((ch + 1) & 1);
            __syncthreads();
        }
    }

    // epilogue: direct float2 stores + bias
    float2 bz[4];
#pragma unroll
    for (int ni = 0; ni < 4; ni++)
        bz[ni] = *(const float2*)&bias[n0 + nb + ni * 8 + 2 * c];

#pragma unroll
    for (int mi = 0; mi < 4; mi++) {
        const int mA = m0 + mb + mi * 16 + g;
        const int mB = mA + 8;
#pragma unroll
        for (int ni = 0; ni < 4; ni++) {
            const int n = n0 + nb + ni * 8 + 2 * c;
            float2 v0 = make_float2(acc[mi][ni][0] + bz[ni].x, acc[mi][ni][1] + bz[ni].y);
            float2 v1 = make_float2(acc[mi][ni][2] + bz[ni].x, acc[mi][ni][3] + bz[ni].y);
            *(float2*)&outp[(size_t)mA * 256 + n] = v0;
            *(float2*)&outp[(size_t)mB * 256 + n] = v1;
        }
    }
}

__global__ __launch_bounds__(256, 2) void gemm_qkv_tc(
    const float* __restrict__ x, const int* __restrict__ pidx,
    const float* __restrict__ Wq, const float* __restrict__ Wk, const float* __restrict__ Wv,
    const float* __restrict__ bq, const float* __restrict__ bk, const float* __restrict__ bv)
{
    extern __shared__ uint32_t smg[];
    const int z = blockIdx.z;
    const float* W  = (z == 0) ? Wq : (z == 1 ? Wk : Wv);
    const float* bi = (z == 0) ? bq : (z == 1 ? bk : bv);
    gemm_tc_core(x, pidx, W, bi, g_qkv + (size_t)z * QKV_ELEMS,
                 blockIdx.x * 128, blockIdx.y * 128, smg);
}

__global__ __launch_bounds__(256, 2) void gemm_proj_tc(
    const int* __restrict__ pinv, const float* __restrict__ Wp,
    const float* __restrict__ bp, float* __restrict__ out)
{
    extern __shared__ uint32_t smg[];
    gemm_tc_core(g_y, pinv, Wp, bp, out, blockIdx.x * 128, blockIdx.y * 128, smg);
}

// ---------------------------------------------------------------------------
// Attention via mma.sync tf32 (round-4 proven, unchanged)
// ---------------------------------------------------------------------------
#define KS_OFF 0
#define VS_OFF (512*36)
#define PS_OFF (VS_OFF + 512*40)
#define SEG_OFF (PS_OFF + 8*1088)
#define ATTN_SMEM ((SEG_OFF + 512) * 4)

__global__ __launch_bounds__(256, 1) void attn_kernel(const int* __restrict__ pbatch)
{
    extern __shared__ uint32_t sm[];
    uint32_t* Ks = sm + KS_OFF;
    uint32_t* Vs = sm + VS_OFF;
    uint32_t* Ps = sm + PS_OFF;
    int*      seg = (int*)(sm + SEG_OFF);

    const int h = blockIdx.x, b = blockIdx.y;
    const float* __restrict__ Qb = g_qkv + (size_t)(b * 512) * 256 + h * 32;
    const float* __restrict__ Kb = Qb + QKV_ELEMS;
    const float* __restrict__ Vb = Qb + 2 * (size_t)QKV_ELEMS;

    const int tid = threadIdx.x;

#pragma unroll
    for (int it = 0; it < 16; it++) {
        int idx = tid + it * 256;
        int j = idx >> 3, d4 = (idx & 7) * 4;
        float4 kv = *(const float4*)(Kb + (size_t)j * 256 + d4);
        float4 vv = *(const float4*)(Vb + (size_t)j * 256 + d4);
        Ks[j*36 + d4+0] = f2tf32(kv.x); Ks[j*36 + d4+1] = f2tf32(kv.y);
        Ks[j*36 + d4+2] = f2tf32(kv.z); Ks[j*36 + d4+3] = f2tf32(kv.w);
        Vs[j*40 + d4+0] = f2tf32(vv.x); Vs[j*40 + d4+1] = f2tf32(vv.y);
        Vs[j*40 + d4+2] = f2tf32(vv.z); Vs[j*40 + d4+3] = f2tf32(vv.w);
    }
    for (int i = tid; i < 512; i += 256) seg[i] = pbatch[b * 512 + i];
    __syncthreads();

    const int warp = tid >> 5, lane = tid & 31;
    const int g = lane >> 2, c = lane & 3;
    uint32_t* Pw = Ps + warp * 1088;
    const float scale = 0.17677669529663688f;

    for (int grp = 0; grp < 4; grp++) {
        const int q0 = warp * 64 + grp * 16;
        const int r0 = q0 + g, r1 = q0 + g + 8;
        const float* Q0 = Qb + (size_t)r0 * 256;
        const float* Q1 = Qb + (size_t)r1 * 256;

        uint32_t aq[4][4];
#pragma unroll
        for (int kt = 0; kt < 4; kt++) {
            aq[kt][0] = f2tf32(Q0[kt*8 + c] * scale);
            aq[kt][1] = f2tf32(Q1[kt*8 + c] * scale);
            aq[kt][2] = f2tf32(Q0[kt*8 + c + 4] * scale);
            aq[kt][3] = f2tf32(Q1[kt*8 + c + 4] * scale);
        }
        const int sq0 = seg[r0], sq1 = seg[r1];

        float m0 = -1e30f, m1 = -1e30f, l0 = 0.f, l1 = 0.f;
        float y[4][4];
#pragma unroll
        for (int n = 0; n < 4; n++)
#pragma unroll
            for (int r = 0; r < 4; r++) y[n][r] = 0.f;

        for (int ch = 0; ch < 8; ch++) {
            const int j0 = ch * 64;
            float s[8][4];
#pragma unroll
            for (int nt = 0; nt < 8; nt++) {
                s[nt][0] = s[nt][1] = s[nt][2] = s[nt][3] = 0.f;
                const int jb = (j0 + nt*8 + g) * 36;
#pragma unroll
                for (int kt = 0; kt < 4; kt++)
                    mma8(s[nt], aq[kt], Ks[jb + kt*8 + c], Ks[jb + kt*8 + c + 4]);
            }

            float cm0 = m0, cm1 = m1;
#pragma unroll
            for (int nt = 0; nt < 8; nt++) {
                const int jA = j0 + nt*8 + 2*c;
                const int sA = seg[jA], sB = seg[jA + 1];
                if (sA == sq0) s[nt][0] = -1e9f;
                if (sB == sq0) s[nt][1] = -1e9f;
                if (sA == sq1) s[nt][2] = -1e9f;
                if (sB == sq1) s[nt][3] = -1e9f;
                cm0 = fmaxf(cm0, fmaxf(s[nt][0], s[nt][1]));
                cm1 = fmaxf(cm1, fmaxf(s[nt][2], s[nt][3]));
            }
            cm0 = fmaxf(cm0, __shfl_xor_sync(0xffffffffu, cm0, 1));
            cm0 = fmaxf(cm0, __shfl_xor_sync(0xffffffffu, cm0, 2));
            cm1 = fmaxf(cm1, __shfl_xor_sync(0xffffffffu, cm1, 1));
            cm1 = fmaxf(cm1, __shfl_xor_sync(0xffffffffu, cm1, 2));

            const float a0 = __expf(m0 - cm0), a1 = __expf(m1 - cm1);
            m0 = cm0; m1 = cm1;
            l0 *= a0; l1 *= a1;
#pragma unroll
            for (int n = 0; n < 4; n++) {
                y[n][0] *= a0; y[n][1] *= a0;
                y[n][2] *= a1; y[n][3] *= a1;
            }

            float ps0 = 0.f, ps1 = 0.f;
#pragma unroll
            for (int nt = 0; nt < 8; nt++) {
                float p0 = __expf(s[nt][0] - m0);
                float p1 = __expf(s[nt][1] - m0);
                float p2 = __expf(s[nt][2] - m1);
                float p3 = __expf(s[nt][3] - m1);
                ps0 += p0 + p1; ps1 += p2 + p3;
                Pw[g*68      + nt*8 + 2*c    ] = f2tf32(p0);
                Pw[g*68      + nt*8 + 2*c + 1] = f2tf32(p1);
                Pw[(g+8)*68  + nt*8 + 2*c    ] = f2tf32(p2);
                Pw[(g+8)*68  + nt*8 + 2*c + 1] = f2tf32(p3);
            }
            l0 += ps0; l1 += ps1;
            __syncwarp();

#pragma unroll
            for (int kt2 = 0; kt2 < 8; kt2++) {
                uint32_t ap[4];
                ap[0] = Pw[g*68     + kt2*8 + c];
                ap[1] = Pw[(g+8)*68 + kt2*8 + c];
                ap[2] = Pw[g*68     + kt2*8 + c + 4];
                ap[3] = Pw[(g+8)*68 + kt2*8 + c + 4];
                const int vb0 = (j0 + kt2*8 + c) * 40 + g;
                const int vb1 = (j0 + kt2*8 + c + 4) * 40 + g;
#pragma unroll
                for (int nt2 = 0; nt2 < 4; nt2++)
                    mma8(y[nt2], ap, Vs[vb0 + nt2*8], Vs[vb1 + nt2*8]);
            }
            __syncwarp();
        }

        l0 += __shfl_xor_sync(0xffffffffu, l0, 1);
        l0 += __shfl_xor_sync(0xffffffffu, l0, 2);
        l1 += __shfl_xor_sync(0xffffffffu, l1, 1);
        l1 += __shfl_xor_sync(0xffffffffu, l1, 2);
        const float inv0 = 1.0f / l0, inv1 = 1.0f / l1;

        float* O0 = g_y + (size_t)(b * 512 + r0) * 256 + h * 32;
        float* O1 = g_y + (size_t)(b * 512 + r1) * 256 + h * 32;
#pragma unroll
        for (int nt2 = 0; nt2 < 4; nt2++) {
            float2 v0 = make_float2(y[nt2][0] * inv0, y[nt2][1] * inv0);
            float2 v1 = make_float2(y[nt2][2] * inv1, y[nt2][3] * inv1);
            *(float2*)&O0[nt2*8 + 2*c] = v0;
            *(float2*)&O1[nt2*8 + 2*c] = v1;
        }
    }
}

// ---------------------------------------------------------------------------

extern "C" void kernel_launch(void* const* d_in, const int* in_sizes, int n_in,
                              void* d_out, int out_size)
{
    const float* x    = (const float*)d_in[0];
    const float* Wq   = (const float*)d_in[1];
    const float* bq   = (const float*)d_in[2];
    const float* Wk   = (const float*)d_in[3];
    const float* bk   = (const float*)d_in[4];
    const float* Wv   = (const float*)d_in[5];
    const float* bv   = (const float*)d_in[6];
    const float* Wp   = (const float*)d_in[7];
    const float* bp   = (const float*)d_in[8];
    const int* pidx   = (const int*)d_in[9];
    const int* pbatch = (const int*)d_in[10];
    const int* pinv   = (const int*)d_in[11];
    float* out = (float*)d_out;

    cudaFuncSetAttribute(gemm_qkv_tc,  cudaFuncAttributeMaxDynamicSharedMemorySize, GEMM_SMEM);
    cudaFuncSetAttribute(gemm_proj_tc, cudaFuncAttributeMaxDynamicSharedMemorySize, GEMM_SMEM);
    cudaFuncSetAttribute(attn_kernel,  cudaFuncAttributeMaxDynamicSharedMemorySize, ATTN_SMEM);

    gemm_qkv_tc<<<dim3(M_ / 128, 2, 3), 256, GEMM_SMEM>>>(x, pidx, Wq, Wk, Wv, bq, bk, bv);
    attn_kernel<<<dim3(H_, B_), 256, ATTN_SMEM>>>(pbatch);
    gemm_proj_tc<<<dim3(NTOT / 128, 2), 256, GEMM_SMEM>>>(pinv, Wp, bp, out);
}